// round 11
// baseline (speedup 1.0000x reference)
#include <cuda_runtime.h>
#include <cstdint>

#define EMB   1024
#define NANT  50
#define PWDIM 64
#define HID   128
#define TK    16
#define NPAD  64
#define NTILE 68          // 64 mention K-tiles + 4 pw K-tiles
#define EPS_DUMMY 1e-7f
#define SLOPE 0.01f

typedef unsigned long long u64;

__device__ __forceinline__ u64 ffma2(u64 a, u64 b, u64 c) {
    u64 d;
    asm("fma.rn.f32x2 %0, %1, %2, %3;" : "=l"(d) : "l"(a), "l"(b), "l"(c));
    return d;
}
__device__ __forceinline__ u64 dup2(float x) {
    u64 d;
    asm("mov.b64 %0, {%1, %1};" : "=l"(d) : "f"(x));
    return d;
}
__device__ __forceinline__ float lo32(u64 v) { return __uint_as_float((unsigned)(v & 0xffffffffull)); }
__device__ __forceinline__ float hi32(u64 v) { return __uint_as_float((unsigned)(v >> 32)); }

__device__ __forceinline__ uint32_t sptr(const void* p) {
    return (uint32_t)__cvta_generic_to_shared(p);
}
__device__ __forceinline__ void cpa16(uint32_t dst, const void* src) {
    asm volatile("cp.async.ca.shared.global [%0], [%1], 16;" :: "r"(dst), "l"(src));
}
__device__ __forceinline__ void cpa_commit() { asm volatile("cp.async.commit_group;"); }
__device__ __forceinline__ void cpa_wait0()  { asm volatile("cp.async.wait_group 0;" ::: "memory"); }

// One block per batch row, 256 threads, 4 ants x 8 hidden per thread (f32x2).
// Registers minimized (target <=64 -> 4 blocks/SM -> 8 warps/SMSP, single wave):
//   - acc: 16 u64 (4 ants x 4 f32x2 pairs)
//   - W staging via cp.async into raw smem (no staging registers), folded
//     (sW = wb + a.*ws) in a smem->smem pass; a-term accumulated from wa there.
//   - B gather register-staged (1 float4/thread), conflict-free STS.32 transpose.
// Pipeline per tile: fold(t) | bar | issue cp.async(t+1)+LDG B(t+1) | FMA(t) |
// wait | bar.
__global__ void __launch_bounds__(256, 4)
anaph_kernel(const float* __restrict__ AM,
             const float* __restrict__ MB,
             const float* __restrict__ PWB,
             const int*   __restrict__ IDX,
             const float* __restrict__ RS,
             const float* __restrict__ W1,
             const float* __restrict__ B1,
             const float* __restrict__ WO,
             const float* __restrict__ BO,
             float* __restrict__ OUT)
{
    __shared__ __align__(16) float sWb[TK][HID];   // raw W1b (or W1pw) tile
    __shared__ __align__(16) float sWs[TK][HID];   // raw W1sim tile
    __shared__ __align__(16) float sWa[TK][HID];   // raw W1a tile
    __shared__ __align__(16) float sW [TK][HID];   // folded Weff
    __shared__ __align__(16) float sB [TK][NPAD];  // gathered mentions (k-major)
    __shared__ __align__(16) float sA [EMB];

    const int tid = threadIdx.x;
    const int b   = blockIdx.x;

    // fold-pass indices: chunk c = tid handles (kw, jc4), chunk tid+256 -> kw+8
    const int kw  = tid >> 5;           // 0..7
    const int jc4 = (tid & 31) * 4;     // float4 column
    // B staging indices
    const int ant = tid & 63;
    const int hq  = tid >> 6;           // 0..3 : which 4-k chunk
    // compute-tile indices
    const int tx = tid & 15;            // 8 hidden per thread
    const int ty = tid >> 4;            // 4 ants per thread

    const uint32_t aWb = sptr(&sWb[kw][jc4]);
    const uint32_t aWs = sptr(&sWs[kw][jc4]);
    const uint32_t aWa = sptr(&sWa[kw][jc4]);

    // gather row base for this thread's ant
    const int myIdx = (ant < NANT) ? IDX[b * NANT + ant] : 0;
    const float* const gsrc = AM + (size_t)myIdx * EMB;
    const float* const psrc = PWB + ((size_t)b * NANT + ant) * PWDIM;

    // stage a-vector
    ((float4*)sA)[tid] = ((const float4*)(MB + (size_t)b * EMB))[tid];

    // ---- cp.async stage of W raw tiles for tile t ----
    auto stageW = [&](int t) {
        if (t < 64) {
            const float* r0 = W1 + (size_t)(t * TK + kw) * HID + jc4;
            cpa16(aWb, r0 + (size_t)EMB * HID);
            cpa16(aWs, r0 + (size_t)2 * EMB * HID);
            cpa16(aWa, r0);
            const float* r1 = r0 + 8 * HID;
            cpa16(aWb + 8 * HID * 4, r1 + (size_t)EMB * HID);
            cpa16(aWs + 8 * HID * 4, r1 + (size_t)2 * EMB * HID);
            cpa16(aWa + 8 * HID * 4, r1);
        } else {
            const float* r0 = W1 + (size_t)(3 * EMB + (t - 64) * TK + kw) * HID + jc4;
            cpa16(aWb, r0);
            cpa16(aWb + 8 * HID * 4, r0 + 8 * HID);
        }
        cpa_commit();
    };
    // ---- register load of B chunk for tile t ----
    auto loadB = [&](int t) -> float4 {
        if (ant >= NANT) return make_float4(0.f, 0.f, 0.f, 0.f);
        if (t < 64) return *(const float4*)(gsrc + t * TK + hq * 4);
        return *(const float4*)(psrc + (t - 64) * TK + hq * 4);
    };

    u64 acc[4][4];
    #pragma unroll
    for (int a = 0; a < 4; ++a)
        #pragma unroll
        for (int p = 0; p < 4; ++p) acc[a][p] = 0ull;

    float4 aa = make_float4(0.f, 0.f, 0.f, 0.f);   // a-term partials (j = jc4..+3)

    stageW(0);
    float4 pf_bv = loadB(0);
    cpa_wait0();
    __syncthreads();                     // sA + raw(0) visible

    for (int t = 0; t < NTILE; ++t) {
        // ---- fold pass: raw -> sW ; B regs -> sB ; a-term from wa ----
        if (t < 64) {
            const int kb = t * TK;
            #pragma unroll
            for (int m = 0; m < 2; ++m) {
                const int k = kw + m * 8;
                const float av = sA[kb + k];
                const float4 wb = *(const float4*)&sWb[k][jc4];
                const float4 ws = *(const float4*)&sWs[k][jc4];
                const float4 wa = *(const float4*)&sWa[k][jc4];
                float4 o;
                o.x = fmaf(av, ws.x, wb.x);
                o.y = fmaf(av, ws.y, wb.y);
                o.z = fmaf(av, ws.z, wb.z);
                o.w = fmaf(av, ws.w, wb.w);
                *(float4*)&sW[k][jc4] = o;
                aa.x = fmaf(av, wa.x, aa.x);
                aa.y = fmaf(av, wa.y, aa.y);
                aa.z = fmaf(av, wa.z, aa.z);
                aa.w = fmaf(av, wa.w, aa.w);
            }
        } else {
            #pragma unroll
            for (int m = 0; m < 2; ++m) {
                const int k = kw + m * 8;
                *(float4*)&sW[k][jc4] = *(const float4*)&sWb[k][jc4];
            }
        }
        sB[hq * 4 + 0][ant] = pf_bv.x;
        sB[hq * 4 + 1][ant] = pf_bv.y;
        sB[hq * 4 + 2][ant] = pf_bv.z;
        sB[hq * 4 + 3][ant] = pf_bv.w;
        __syncthreads();                 // sW, sB ready; raws fully consumed

        if (t + 1 < NTILE) {
            stageW(t + 1);               // cp.async into raws under the FMAs
            pf_bv = loadB(t + 1);
        }

        #pragma unroll
        for (int k = 0; k < TK; ++k) {
            const ulonglong2 wA = *(const ulonglong2*)&sW[k][tx * 4];
            const ulonglong2 wB = *(const ulonglong2*)&sW[k][64 + tx * 4];
            const float4 bv = *(const float4*)&sB[k][ty * 4];
            u64 bd;
            bd = dup2(bv.x);
            acc[0][0] = ffma2(bd, wA.x, acc[0][0]); acc[0][1] = ffma2(bd, wA.y, acc[0][1]);
            acc[0][2] = ffma2(bd, wB.x, acc[0][2]); acc[0][3] = ffma2(bd, wB.y, acc[0][3]);
            bd = dup2(bv.y);
            acc[1][0] = ffma2(bd, wA.x, acc[1][0]); acc[1][1] = ffma2(bd, wA.y, acc[1][1]);
            acc[1][2] = ffma2(bd, wB.x, acc[1][2]); acc[1][3] = ffma2(bd, wB.y, acc[1][3]);
            bd = dup2(bv.z);
            acc[2][0] = ffma2(bd, wA.x, acc[2][0]); acc[2][1] = ffma2(bd, wA.y, acc[2][1]);
            acc[2][2] = ffma2(bd, wB.x, acc[2][2]); acc[2][3] = ffma2(bd, wB.y, acc[2][3]);
            bd = dup2(bv.w);
            acc[3][0] = ffma2(bd, wA.x, acc[3][0]); acc[3][1] = ffma2(bd, wA.y, acc[3][1]);
            acc[3][2] = ffma2(bd, wB.x, acc[3][2]); acc[3][3] = ffma2(bd, wB.y, acc[3][3]);
        }

        if (t + 1 < NTILE) cpa_wait0();  // raw(t+1) arrived
        __syncthreads();                 // all warps done with sW/sB of tile t
    }

    // ---- a-term reduction: reuse sB storage (last tile fully consumed) ----
    float* sva = &sB[0][0];              // 8 groups x 128 j  (4KB fits in sB)
    *(float4*)(sva + kw * HID + jc4) = aa;
    __syncthreads();

    float bias_lo[4], bias_hi[4], wlo[4], whi[4];
    {
        float4 va_a = make_float4(0.f, 0.f, 0.f, 0.f);
        float4 va_b = make_float4(0.f, 0.f, 0.f, 0.f);
        #pragma unroll
        for (int g = 0; g < 8; ++g) {
            const float4 v1 = *(const float4*)(sva + g * HID + tx * 4);
            const float4 v2 = *(const float4*)(sva + g * HID + 64 + tx * 4);
            va_a.x += v1.x; va_a.y += v1.y; va_a.z += v1.z; va_a.w += v1.w;
            va_b.x += v2.x; va_b.y += v2.y; va_b.z += v2.z; va_b.w += v2.w;
        }
        const float4 b1a = *(const float4*)(B1 + tx * 4);
        const float4 b1b = *(const float4*)(B1 + 64 + tx * 4);
        const float4 woa = *(const float4*)(WO + tx * 4);
        const float4 wob = *(const float4*)(WO + 64 + tx * 4);
        bias_lo[0] = va_a.x + b1a.x;  bias_hi[0] = va_a.y + b1a.y;
        bias_lo[1] = va_a.z + b1a.z;  bias_hi[1] = va_a.w + b1a.w;
        bias_lo[2] = va_b.x + b1b.x;  bias_hi[2] = va_b.y + b1b.y;
        bias_lo[3] = va_b.z + b1b.z;  bias_hi[3] = va_b.w + b1b.w;
        wlo[0] = woa.x; whi[0] = woa.y; wlo[1] = woa.z; whi[1] = woa.w;
        wlo[2] = wob.x; whi[2] = wob.y; wlo[3] = wob.z; whi[3] = wob.w;
    }
    const float bo = BO[0];

    #pragma unroll
    for (int a = 0; a < 4; ++a) {
        float s = 0.f;
        #pragma unroll
        for (int p = 0; p < 4; ++p) {
            float l = lo32(acc[a][p]) + bias_lo[p];
            float h = hi32(acc[a][p]) + bias_hi[p];
            l = (l > 0.f) ? l : SLOPE * l;
            h = (h > 0.f) ? h : SLOPE * h;
            s = fmaf(l, wlo[p], s);
            s = fmaf(h, whi[p], s);
        }
        #pragma unroll
        for (int off = 8; off > 0; off >>= 1)
            s += __shfl_down_sync(0xffffffffu, s, off, 16);
        if (tx == 0) {
            const int ai = ty * 4 + a;
            if (ai < NANT)
                OUT[b * (NANT + 1) + 1 + ai] = RS[b * NANT + ai] + s + bo;
        }
    }
    if (tid == 0) OUT[b * (NANT + 1)] = EPS_DUMMY;
}

extern "C" void kernel_launch(void* const* d_in, const int* in_sizes, int n_in,
                              void* d_out, int out_size) {
    const float* AM  = (const float*)d_in[0];   // all_mentions        [10000,1024]
    const float* MB  = (const float*)d_in[1];   // mentions_batch      [512,1024]
    const float* PWB = (const float*)d_in[2];   // pw_batch            [512,50,64]
    const int*   IDX = (const int*)  d_in[3];   // top_indices_batch   [512,50] int32
    const float* RS  = (const float*)d_in[4];   // top_rough_scores    [512,50]
    const float* W1  = (const float*)d_in[5];   // [3136,128]
    const float* B1  = (const float*)d_in[6];   // [128]
    const float* WO  = (const float*)d_in[7];   // [128,1]
    const float* BO  = (const float*)d_in[8];   // [1]
    float* OUT = (float*)d_out;                 // [512,51]

    const int batch = in_sizes[4] / NANT;       // 512
    anaph_kernel<<<batch, 256>>>(AM, MB, PWB, IDX, RS, W1, B1, WO, BO, OUT);
}